// round 8
// baseline (speedup 1.0000x reference)
#include <cuda_runtime.h>
#include <cstdint>

#define N_BUSES 2000
#define MAX_BN     131072
#define MAX_B      64
#define MAX_LOSERS 8192
#define MAX_FB     1024
#define MAX_BLOCKS 1024
#define NT         256
#define TAB_BITS   27
#define TAB_SIZE   (1 << TAB_BITS)      // keys < 32*2000*2000 < 2^27
#define EDGE_BITS  18
#define EDGE_MASK  0x3FFFFull

// Static device scratch (zero-initialized at module load; no runtime allocation).
__device__ unsigned long long g_tab[TAB_SIZE];    // (epoch<<18)|(edge+1); direct-mapped
__device__ int                g_losers[MAX_LOSERS];
__device__ int                g_nlos;
__device__ int                g_fb[MAX_FB];       // buses with vm==0 (deferred D2/D3)
__device__ int                g_nfb;
__device__ float2             g_YV[MAX_BN];       // per-bus YV accumulator (complex)
__device__ float2             g_Smean[MAX_B];
__device__ float              g_Vmmean[MAX_B];
__device__ double             g_part1[MAX_BLOCKS][3];  // k1 partials: d2, d3, mse
__device__ double             g_part2[MAX_BLOCKS][2];  // k2 partials: d1r, d1i
__device__ unsigned long long g_epoch;            // bumped once per call (k2 finalize)
__device__ unsigned           g_done1, g_done2;

__device__ __forceinline__ void red_add_v2(float2* addr, float vx, float vy)
{
    asm volatile("red.global.add.v2.f32 [%0], {%1, %2};"
                 :: "l"(addr), "f"(vx), "f"(vy) : "memory");
}

// ---------------------------------------------------------------------------
// K1: edges (scatter + dedup) | per-batch means | MSE + D2 + D3 partials.
//     Last-done block subtracts loser edge contributions from YV.
// ---------------------------------------------------------------------------
__global__ void k1_build(const float* __restrict__ x,
                         const float* __restrict__ ea,
                         const int*   __restrict__ ei,
                         const float* __restrict__ outputs,
                         const float* __restrict__ labels,
                         int B, int BN, int BE, int E)
{
    const int tid = threadIdx.x;
    const int lane = tid & 31, wid = tid >> 5;
    const unsigned long long tag = g_epoch + 1ull;

    // --- blocks [0,B): per-batch means of S and Vm ---
    if (blockIdx.x < B) {
        const int b = blockIdx.x;
        float sr = 0.f, si = 0.f, vm = 0.f;
        for (int i = tid; i < N_BUSES; i += NT) {
            const float* p = x + (size_t)(b * N_BUSES + i) * 6;
            sr += p[0]; si += p[1]; vm += p[2];
        }
        for (int o = 16; o > 0; o >>= 1) {
            sr += __shfl_down_sync(0xffffffffu, sr, o);
            si += __shfl_down_sync(0xffffffffu, si, o);
            vm += __shfl_down_sync(0xffffffffu, vm, o);
        }
        __shared__ float shm[3][NT / 32];
        if (lane == 0) { shm[0][wid] = sr; shm[1][wid] = si; shm[2][wid] = vm; }
        __syncthreads();
        if (wid == 0) {
            sr = (lane < NT / 32) ? shm[0][lane] : 0.f;
            si = (lane < NT / 32) ? shm[1][lane] : 0.f;
            vm = (lane < NT / 32) ? shm[2][lane] : 0.f;
            for (int o = 4; o > 0; o >>= 1) {
                sr += __shfl_down_sync(0xffffffffu, sr, o);
                si += __shfl_down_sync(0xffffffffu, si, o);
                vm += __shfl_down_sync(0xffffffffu, vm, o);
            }
            if (lane == 0) {
                const float inv = 1.0f / (float)N_BUSES;
                g_Smean[b]  = make_float2(sr * inv, si * inv);
                g_Vmmean[b] = vm * inv;
            }
        }
    }

    // --- one edge per thread: scatter + dedup ---
    const int e = blockIdx.x * NT + tid;
    if (e < BE) {
        const int i = ei[e]      % N_BUSES;
        const int j = ei[BE + e] % N_BUSES;
        const int b = e / E;

        const float2 a2v = *(const float2*)(ea + 2 * e);
        const float2 v2  = *(const float2*)(outputs + 2 * (b * N_BUSES + j));
        red_add_v2(&g_YV[b * N_BUSES + i],
                   a2v.x * v2.x - a2v.y * v2.y,
                   a2v.x * v2.y + a2v.y * v2.x);

        const int key = (b * N_BUSES + i) * N_BUSES + j;     // < 2^27
        const unsigned long long newval = (tag << EDGE_BITS) | (unsigned)(e + 1);
        const unsigned long long old = atomicMax(&g_tab[key], newval);
        if ((old >> EDGE_BITS) == tag) {                      // duplicate this call
            const int loser = (old > newval) ? e : (int)(old & EDGE_MASK) - 1;
            const int li = atomicAdd(&g_nlos, 1);
            if (li < MAX_LOSERS) g_losers[li] = loser;
        }
    }

    // --- k1-independent bus terms: MSE, D2, D3 (first 250 blocks) ---
    double p2 = 0, p3 = 0, pm = 0;
    const int idx = blockIdx.x * NT + tid;
    if (idx < BN) {
        const float2 v2 = *(const float2*)(outputs + 2 * idx);
        const float2 l2 = *(const float2*)(labels  + 2 * idx);
        const float* p = x + (size_t)idx * 6;
        const float vm  = p[2];
        const float bt1 = p[4], bt2 = p[5];

        const float e0 = v2.x - l2.x, e1 = v2.y - l2.y;
        pm = (double)(e0 * e0) + (double)(e1 * e1);

        if (vm != 0.f) {
            const float vminv = 1.f / vm;
            const float vmag  = sqrtf(v2.x * v2.x + v2.y * v2.y);
            p2 = (double)(fabsf(vmag * (bt1 + bt2) - vm) * vminv);
            p3 = (double)(fabsf(v2.y * bt2) * vminv);
        } else {                                   // needs Vmmean: defer to k2
            const int fi = atomicAdd(&g_nfb, 1);
            if (fi < MAX_FB) g_fb[fi] = idx;
        }
    }
    for (int o = 16; o > 0; o >>= 1) {
        p2 += __shfl_down_sync(0xffffffffu, p2, o);
        p3 += __shfl_down_sync(0xffffffffu, p3, o);
        pm += __shfl_down_sync(0xffffffffu, pm, o);
    }
    __shared__ double shd[3][NT / 32];
    if (lane == 0) { shd[0][wid] = p2; shd[1][wid] = p3; shd[2][wid] = pm; }
    __syncthreads();
    if (wid == 0) {
        p2 = (lane < NT / 32) ? shd[0][lane] : 0.0;
        p3 = (lane < NT / 32) ? shd[1][lane] : 0.0;
        pm = (lane < NT / 32) ? shd[2][lane] : 0.0;
        for (int o = 4; o > 0; o >>= 1) {
            p2 += __shfl_down_sync(0xffffffffu, p2, o);
            p3 += __shfl_down_sync(0xffffffffu, p3, o);
            pm += __shfl_down_sync(0xffffffffu, pm, o);
        }
        if (lane == 0) {
            g_part1[blockIdx.x][0] = p2;
            g_part1[blockIdx.x][1] = p3;
            g_part1[blockIdx.x][2] = pm;
        }
    }

    // --- last-done block subtracts loser contributions ---
    __shared__ int s_last;
    __syncthreads();
    if (tid == 0) {
        __threadfence();
        s_last = (atomicAdd(&g_done1, 1u) == gridDim.x - 1u);
    }
    __syncthreads();
    if (s_last) {
        __threadfence();
        const int n = g_nlos;
        for (int t = tid; t < n && t < MAX_LOSERS; t += NT) {
            const int le = g_losers[t];
            const int i = ei[le]      % N_BUSES;
            const int j = ei[BE + le] % N_BUSES;
            const int b = le / E;
            const float2 a2v = *(const float2*)(ea + 2 * le);
            const float2 v2  = *(const float2*)(outputs + 2 * (b * N_BUSES + j));
            red_add_v2(&g_YV[b * N_BUSES + i],
                       -(a2v.x * v2.x - a2v.y * v2.y),
                       -(a2v.x * v2.y + a2v.y * v2.x));
        }
        __syncthreads();
        if (tid == 0) { g_done1 = 0u; g_nlos = 0; }
    }
}

// ---------------------------------------------------------------------------
// K2: D1 only (needs YV); read-then-clear YV; last-done block merges all
//     partials + deferred fallbacks, finalizes, bumps epoch.
// ---------------------------------------------------------------------------
__global__ void k2_d1(const float* __restrict__ x,
                      const float* __restrict__ outputs,
                      float* __restrict__ out, int out_size,
                      int BN, int nb1)
{
    const int tid = threadIdx.x;
    const int idx = blockIdx.x * NT + tid;
    const int lane = tid & 31, wid = tid >> 5;
    double a0 = 0, a1 = 0;

    if (idx < BN) {
        const int b = idx / N_BUSES;
        const float2 v2 = *(const float2*)(outputs + 2 * idx);
        const float2 yv = g_YV[idx];
        g_YV[idx] = make_float2(0.f, 0.f);            // clean for next call
        const float sp_re = v2.x * yv.x + v2.y * yv.y;   // Spred = V * conj(YV)
        const float sp_im = v2.y * yv.x - v2.x * yv.y;
        const float* p = x + (size_t)idx * 6;
        const float sr = p[0], si = p[1];
        const float bt0 = p[3], bt1 = p[4];

        float sn;
        if (sr != 0.f || si != 0.f) {
            sn = 1.f / sqrtf(sr * sr + si * si);
        } else {
            const float2 sm = g_Smean[b];
            sn = 1.f / sqrtf(sm.x * sm.x + sm.y * sm.y);
        }
        const float dr = sp_re - sr, di = sp_im - si;
        const float r1r = (dr * dr - di * di) * bt0;
        const float r1i = (2.f * dr * di) * bt0;
        const float r2  = dr * dr * bt1;
        a0 = (double)(sn * (r1r + r2));
        a1 = (double)(sn * r1i);
    }

    for (int o = 16; o > 0; o >>= 1) {
        a0 += __shfl_down_sync(0xffffffffu, a0, o);
        a1 += __shfl_down_sync(0xffffffffu, a1, o);
    }
    __shared__ double shd[2][NT / 32];
    if (lane == 0) { shd[0][wid] = a0; shd[1][wid] = a1; }
    __syncthreads();
    if (wid == 0) {
        a0 = (lane < NT / 32) ? shd[0][lane] : 0.0;
        a1 = (lane < NT / 32) ? shd[1][lane] : 0.0;
        for (int o = 4; o > 0; o >>= 1) {
            a0 += __shfl_down_sync(0xffffffffu, a0, o);
            a1 += __shfl_down_sync(0xffffffffu, a1, o);
        }
        if (lane == 0) {
            g_part2[blockIdx.x][0] = a0;
            g_part2[blockIdx.x][1] = a1;
        }
    }

    // --- last-done block: merge everything, finalize ---
    __shared__ int s_last;
    __syncthreads();
    if (tid == 0) {
        __threadfence();
        s_last = (atomicAdd(&g_done2, 1u) == gridDim.x - 1u);
    }
    __syncthreads();
    if (s_last) {
        __threadfence();
        double s0 = 0, s1 = 0, s2 = 0, s3 = 0, s4 = 0;
        for (int i = tid; i < nb1; i += NT) {
            s2 += g_part1[i][0]; s3 += g_part1[i][1]; s4 += g_part1[i][2];
        }
        for (int i = tid; i < (int)gridDim.x; i += NT) {
            s0 += g_part2[i][0]; s1 += g_part2[i][1];
        }
        // deferred vm==0 buses (expected none)
        const int nfb = g_nfb;
        for (int t = tid; t < nfb && t < MAX_FB; t += NT) {
            const int bi = g_fb[t];
            const int b = bi / N_BUSES;
            const float2 v2 = *(const float2*)(outputs + 2 * bi);
            const float* p = x + (size_t)bi * 6;
            const float vm = p[2], bt1 = p[4], bt2 = p[5];
            const float vminv = (vm != 0.f) ? (1.f / vm) : (1.f / g_Vmmean[b]);
            const float vmag  = sqrtf(v2.x * v2.x + v2.y * v2.y);
            s2 += (double)(fabsf(vmag * (bt1 + bt2) - vm) * vminv);
            s3 += (double)(fabsf(v2.y * bt2) * vminv);
        }
        for (int o = 16; o > 0; o >>= 1) {
            s0 += __shfl_down_sync(0xffffffffu, s0, o);
            s1 += __shfl_down_sync(0xffffffffu, s1, o);
            s2 += __shfl_down_sync(0xffffffffu, s2, o);
            s3 += __shfl_down_sync(0xffffffffu, s3, o);
            s4 += __shfl_down_sync(0xffffffffu, s4, o);
        }
        __shared__ double sh2[5][NT / 32];
        if (lane == 0) {
            sh2[0][wid] = s0; sh2[1][wid] = s1; sh2[2][wid] = s2;
            sh2[3][wid] = s3; sh2[4][wid] = s4;
        }
        __syncthreads();
        if (tid == 0) {
            s0 = s1 = s2 = s3 = s4 = 0.0;
            for (int w = 0; w < NT / 32; w++) {
                s0 += sh2[0][w]; s1 += sh2[1][w]; s2 += sh2[2][w];
                s3 += sh2[3][w]; s4 += sh2[4][w];
            }
            const double inv = 1.0 / (double)BN;
            const double d1r = s0 * inv;
            const double d1i = s1 * inv;
            const double d2  = s2 * inv;
            const double d3  = s3 * inv;
            const double mse = s4 / (double)(2 * BN);
            const double pr = d1r + d2 + d3;   // W1=W2=W3=1
            const double pi = d1i;
            const double lr = mse + 0.1 * pr;  // LMBDA = 0.1
            const double li = 0.1 * pi;
            if (out_size >= 10) {
                out[0] = (float)lr;  out[1] = (float)li;
                out[2] = (float)pr;  out[3] = (float)pi;
                out[4] = (float)d1r; out[5] = (float)d1i;
                out[6] = (float)d2;  out[7] = 0.f;
                out[8] = (float)d3;  out[9] = 0.f;
            } else {
                out[0] = (float)lr;
                if (out_size > 1) out[1] = (float)pr;
                if (out_size > 2) out[2] = (float)d1r;
                if (out_size > 3) out[3] = (float)d2;
                if (out_size > 4) out[4] = (float)d3;
            }
            g_done2 = 0u;
            g_nfb = 0;
            g_epoch = g_epoch + 1ull;          // 46-bit epoch: never wraps
        }
    }
}

// ---------------------------------------------------------------------------
extern "C" void kernel_launch(void* const* d_in, const int* in_sizes, int n_in,
                              void* d_out, int out_size)
{
    const float* x       = (const float*)d_in[0];
    const float* ea      = (const float*)d_in[1];
    const int*   ei      = (const int*)  d_in[2];
    const float* outputs = (const float*)d_in[3];
    const float* labels  = (const float*)d_in[4];

    const int BN = in_sizes[3] / 2;        // B * N_BUSES
    const int B  = BN / N_BUSES;
    const int BE = in_sizes[2] / 2;        // B * E
    const int E  = BE / B;

    const int nbEdge = (BE + NT - 1) / NT; // 750
    const int nbBus  = (BN + NT - 1) / NT; // 250
    const int nb1    = (nbEdge < MAX_BLOCKS) ? nbEdge : MAX_BLOCKS;

    k1_build<<<nbEdge, NT>>>(x, ea, ei, outputs, labels, B, BN, BE, E);
    k2_d1<<<nbBus, NT>>>(x, outputs, (float*)d_out, out_size, BN, nb1);
}

// round 11
// speedup vs baseline: 1.2452x; 1.2452x over previous
#include <cuda_runtime.h>
#include <cstdint>

#define N_BUSES 2000
#define MAX_BN     131072
#define MAX_B      64
#define MAX_LOSERS 8192
#define MAX_BLOCKS 1024
#define NT         256
#define TAB_BITS   27
#define TAB_SIZE   (1 << TAB_BITS)      // keys < 32*2000*2000 < 2^27
#define EDGE_BITS  18
#define EDGE_MASK  0x3FFFFull

// Static device scratch (zero-initialized at module load; no runtime allocation).
__device__ unsigned long long g_tab[TAB_SIZE];    // (epoch<<18)|(edge+1); direct-mapped
__device__ int                g_losers[MAX_LOSERS];
__device__ int                g_nlos;
__device__ float2             g_YV[MAX_BN];       // per-bus YV accumulator (complex)
__device__ float2             g_Smean[MAX_B];
__device__ float              g_Vmmean[MAX_B];
__device__ double             g_part[MAX_BLOCKS][5];  // k2 partials: d1r,d1i,d2,d3,mse
__device__ unsigned long long g_epoch;            // bumped once per call (k2 finalize)
__device__ unsigned           g_done1, g_done2;

__device__ __forceinline__ void red_add_v2(float2* addr, float vx, float vy)
{
    asm volatile("red.global.add.v2.f32 [%0], {%1, %2};"
                 :: "l"(addr), "f"(vx), "f"(vy) : "memory");
}

// ---------------------------------------------------------------------------
// K1: per-batch means | 2 edges/thread: scatter (red.v2) + dedup (atomicMax).
//     Last-done block subtracts loser contributions.
// ---------------------------------------------------------------------------
__global__ void k1_build(const float* __restrict__ x,
                         const float* __restrict__ ea,
                         const int*   __restrict__ ei,
                         const float* __restrict__ outputs,
                         int B, int BE, int E)
{
    const int tid = threadIdx.x;
    const int lane = tid & 31, wid = tid >> 5;
    const unsigned long long tag = g_epoch + 1ull;

    // --- blocks [0,B): per-batch means of S and Vm ---
    if (blockIdx.x < B) {
        const int b = blockIdx.x;
        float sr = 0.f, si = 0.f, vm = 0.f;
        for (int i = tid; i < N_BUSES; i += NT) {
            const float* p = x + (size_t)(b * N_BUSES + i) * 6;
            sr += p[0]; si += p[1]; vm += p[2];
        }
        for (int o = 16; o > 0; o >>= 1) {
            sr += __shfl_down_sync(0xffffffffu, sr, o);
            si += __shfl_down_sync(0xffffffffu, si, o);
            vm += __shfl_down_sync(0xffffffffu, vm, o);
        }
        __shared__ float shm[3][NT / 32];
        if (lane == 0) { shm[0][wid] = sr; shm[1][wid] = si; shm[2][wid] = vm; }
        __syncthreads();
        if (wid == 0) {
            sr = (lane < NT / 32) ? shm[0][lane] : 0.f;
            si = (lane < NT / 32) ? shm[1][lane] : 0.f;
            vm = (lane < NT / 32) ? shm[2][lane] : 0.f;
            for (int o = 4; o > 0; o >>= 1) {
                sr += __shfl_down_sync(0xffffffffu, sr, o);
                si += __shfl_down_sync(0xffffffffu, si, o);
                vm += __shfl_down_sync(0xffffffffu, vm, o);
            }
            if (lane == 0) {
                const float inv = 1.0f / (float)N_BUSES;
                g_Smean[b]  = make_float2(sr * inv, si * inv);
                g_Vmmean[b] = vm * inv;
            }
        }
    }

    // --- two edges per thread: batched loads, overlapped atomics ---
    const int e0 = 2 * (blockIdx.x * NT + tid);
    if (e0 + 1 < BE) {
        const int2  srcs = *(const int2*)(ei + e0);        // ei[0, e0..e0+1]
        const int2  dsts = *(const int2*)(ei + BE + e0);   // ei[1, e0..e0+1]
        const float4 aa  = *(const float4*)(ea + 2 * e0);  // adm for both edges

        const int iA = srcs.x % N_BUSES, jA = dsts.x % N_BUSES, bA = e0 / E;
        const int iB = srcs.y % N_BUSES, jB = dsts.y % N_BUSES, bB = (e0 + 1) / E;

        // two independent gathers in flight together
        const float2 vA = *(const float2*)(outputs + 2 * (bA * N_BUSES + jA));
        const float2 vB = *(const float2*)(outputs + 2 * (bB * N_BUSES + jB));

        red_add_v2(&g_YV[bA * N_BUSES + iA],
                   aa.x * vA.x - aa.y * vA.y, aa.x * vA.y + aa.y * vA.x);
        red_add_v2(&g_YV[bB * N_BUSES + iB],
                   aa.z * vB.x - aa.w * vB.y, aa.z * vB.y + aa.w * vB.x);

        const int keyA = (bA * N_BUSES + iA) * N_BUSES + jA;
        const int keyB = (bB * N_BUSES + iB) * N_BUSES + jB;
        const unsigned long long nvA = (tag << EDGE_BITS) | (unsigned)(e0 + 1);
        const unsigned long long nvB = (tag << EDGE_BITS) | (unsigned)(e0 + 2);
        const unsigned long long oldA = atomicMax(&g_tab[keyA], nvA);
        const unsigned long long oldB = atomicMax(&g_tab[keyB], nvB);
        if ((oldA >> EDGE_BITS) == tag) {
            const int loser = (oldA > nvA) ? e0 : (int)(oldA & EDGE_MASK) - 1;
            const int li = atomicAdd(&g_nlos, 1);
            if (li < MAX_LOSERS) g_losers[li] = loser;
        }
        if ((oldB >> EDGE_BITS) == tag) {
            const int loser = (oldB > nvB) ? (e0 + 1) : (int)(oldB & EDGE_MASK) - 1;
            const int li = atomicAdd(&g_nlos, 1);
            if (li < MAX_LOSERS) g_losers[li] = loser;
        }
    } else if (e0 < BE) {                                  // odd remainder
        const int i = ei[e0] % N_BUSES, j = ei[BE + e0] % N_BUSES, b = e0 / E;
        const float2 av = *(const float2*)(ea + 2 * e0);
        const float2 v  = *(const float2*)(outputs + 2 * (b * N_BUSES + j));
        red_add_v2(&g_YV[b * N_BUSES + i],
                   av.x * v.x - av.y * v.y, av.x * v.y + av.y * v.x);
        const int key = (b * N_BUSES + i) * N_BUSES + j;
        const unsigned long long nv = (tag << EDGE_BITS) | (unsigned)(e0 + 1);
        const unsigned long long old = atomicMax(&g_tab[key], nv);
        if ((old >> EDGE_BITS) == tag) {
            const int loser = (old > nv) ? e0 : (int)(old & EDGE_MASK) - 1;
            const int li = atomicAdd(&g_nlos, 1);
            if (li < MAX_LOSERS) g_losers[li] = loser;
        }
    }

    // --- last-done block subtracts loser contributions ---
    __shared__ int s_last;
    __syncthreads();
    if (tid == 0) {
        __threadfence();
        s_last = (atomicAdd(&g_done1, 1u) == gridDim.x - 1u);
    }
    __syncthreads();
    if (s_last) {
        __threadfence();
        const int n = g_nlos;
        for (int t = tid; t < n && t < MAX_LOSERS; t += NT) {
            const int le = g_losers[t];
            const int i = ei[le] % N_BUSES, j = ei[BE + le] % N_BUSES, b = le / E;
            const float2 av = *(const float2*)(ea + 2 * le);
            const float2 v  = *(const float2*)(outputs + 2 * (b * N_BUSES + j));
            red_add_v2(&g_YV[b * N_BUSES + i],
                       -(av.x * v.x - av.y * v.y), -(av.x * v.y + av.y * v.x));
        }
        __syncthreads();
        if (tid == 0) { g_done1 = 0u; g_nlos = 0; }
    }
}

// ---------------------------------------------------------------------------
// K2: 2 buses/thread, fully vectorized; all 5 terms; read-then-clear YV;
//     last-done block merges partials, finalizes, bumps epoch.
// ---------------------------------------------------------------------------
__global__ void k2_terms(const float* __restrict__ x,
                         const float* __restrict__ outputs,
                         const float* __restrict__ labels,
                         float* __restrict__ out, int out_size, int BN)
{
    const int tid = threadIdx.x;
    const int lane = tid & 31, wid = tid >> 5;
    const int i0 = 2 * (blockIdx.x * NT + tid);
    double a0 = 0, a1 = 0, a2 = 0, a3 = 0, a4 = 0;

    if (i0 + 1 < BN) {
        // ---- batched vector loads (high MLP) ----
        const float4 vv  = *(const float4*)(outputs + 2 * i0);   // V for both buses
        const float4 ll  = *(const float4*)(labels  + 2 * i0);
        const float4* yvp = (const float4*)&g_YV[i0];
        const float4 yv2 = *yvp;
        const float4* px = (const float4*)(x + (size_t)i0 * 6);  // 3 vecs = 2 rows
        const float4 xa = px[0], xb = px[1], xc = px[2];
        *(float4*)&g_YV[i0] = make_float4(0.f, 0.f, 0.f, 0.f);   // clean for next call

        const int b = i0 / N_BUSES;      // i0 even => both buses in same batch
        const float2 sm = g_Smean[b];
        const float smn = 1.f / sqrtf(sm.x * sm.x + sm.y * sm.y);
        const float vmm = 1.f / g_Vmmean[b];

        // ---- bus A: x row = {xa.x,xa.y,xa.z,xa.w,xb.x,xb.y} ----
        {
            const float vr = vv.x, vi = vv.y;
            const float sr = xa.x, si = xa.y, vm = xa.z;
            const float bt0 = xa.w, bt1 = xb.x, bt2 = xb.y;
            const float sp_re = vr * yv2.x + vi * yv2.y;
            const float sp_im = vi * yv2.x - vr * yv2.y;
            const float sn = (sr != 0.f || si != 0.f)
                           ? (1.f / sqrtf(sr * sr + si * si)) : smn;
            const float dr = sp_re - sr, di = sp_im - si;
            a0 += (double)(sn * ((dr * dr - di * di) * bt0 + dr * dr * bt1));
            a1 += (double)(sn * (2.f * dr * di) * bt0);
            const float vminv = (vm != 0.f) ? (1.f / vm) : vmm;
            const float vmag  = sqrtf(vr * vr + vi * vi);
            a2 += (double)(fabsf(vmag * (bt1 + bt2) - vm) * vminv);
            a3 += (double)(fabsf(vi * bt2) * vminv);
            const float e0 = vr - ll.x, e1 = vi - ll.y;
            a4 += (double)(e0 * e0) + (double)(e1 * e1);
        }
        // ---- bus B: x row = {xb.z,xb.w,xc.x,xc.y,xc.z,xc.w} ----
        {
            const float vr = vv.z, vi = vv.w;
            const float sr = xb.z, si = xb.w, vm = xc.x;
            const float bt0 = xc.y, bt1 = xc.z, bt2 = xc.w;
            const float sp_re = vr * yv2.z + vi * yv2.w;
            const float sp_im = vi * yv2.z - vr * yv2.w;
            const float sn = (sr != 0.f || si != 0.f)
                           ? (1.f / sqrtf(sr * sr + si * si)) : smn;
            const float dr = sp_re - sr, di = sp_im - si;
            a0 += (double)(sn * ((dr * dr - di * di) * bt0 + dr * dr * bt1));
            a1 += (double)(sn * (2.f * dr * di) * bt0);
            const float vminv = (vm != 0.f) ? (1.f / vm) : vmm;
            const float vmag  = sqrtf(vr * vr + vi * vi);
            a2 += (double)(fabsf(vmag * (bt1 + bt2) - vm) * vminv);
            a3 += (double)(fabsf(vi * bt2) * vminv);
            const float e0 = vr - ll.z, e1 = vi - ll.w;
            a4 += (double)(e0 * e0) + (double)(e1 * e1);
        }
    } else if (i0 < BN) {                 // odd remainder bus
        const int b = i0 / N_BUSES;
        const float2 v2 = *(const float2*)(outputs + 2 * i0);
        const float2 l2 = *(const float2*)(labels + 2 * i0);
        const float2 yv = g_YV[i0];
        g_YV[i0] = make_float2(0.f, 0.f);
        const float* p = x + (size_t)i0 * 6;
        const float sr = p[0], si = p[1], vm = p[2];
        const float bt0 = p[3], bt1 = p[4], bt2 = p[5];
        const float sp_re = v2.x * yv.x + v2.y * yv.y;
        const float sp_im = v2.y * yv.x - v2.x * yv.y;
        float sn;
        if (sr != 0.f || si != 0.f) sn = 1.f / sqrtf(sr * sr + si * si);
        else { const float2 sm = g_Smean[b]; sn = 1.f / sqrtf(sm.x * sm.x + sm.y * sm.y); }
        const float dr = sp_re - sr, di = sp_im - si;
        a0 = (double)(sn * ((dr * dr - di * di) * bt0 + dr * dr * bt1));
        a1 = (double)(sn * (2.f * dr * di) * bt0);
        const float vminv = (vm != 0.f) ? (1.f / vm) : (1.f / g_Vmmean[b]);
        const float vmag  = sqrtf(v2.x * v2.x + v2.y * v2.y);
        a2 = (double)(fabsf(vmag * (bt1 + bt2) - vm) * vminv);
        a3 = (double)(fabsf(v2.y * bt2) * vminv);
        const float e0 = v2.x - l2.x, e1 = v2.y - l2.y;
        a4 = (double)(e0 * e0) + (double)(e1 * e1);
    }

    for (int o = 16; o > 0; o >>= 1) {
        a0 += __shfl_down_sync(0xffffffffu, a0, o);
        a1 += __shfl_down_sync(0xffffffffu, a1, o);
        a2 += __shfl_down_sync(0xffffffffu, a2, o);
        a3 += __shfl_down_sync(0xffffffffu, a3, o);
        a4 += __shfl_down_sync(0xffffffffu, a4, o);
    }
    __shared__ double shd[5][NT / 32];
    if (lane == 0) {
        shd[0][wid] = a0; shd[1][wid] = a1; shd[2][wid] = a2;
        shd[3][wid] = a3; shd[4][wid] = a4;
    }
    __syncthreads();
    if (wid == 0) {
        a0 = (lane < NT / 32) ? shd[0][lane] : 0.0;
        a1 = (lane < NT / 32) ? shd[1][lane] : 0.0;
        a2 = (lane < NT / 32) ? shd[2][lane] : 0.0;
        a3 = (lane < NT / 32) ? shd[3][lane] : 0.0;
        a4 = (lane < NT / 32) ? shd[4][lane] : 0.0;
        for (int o = 4; o > 0; o >>= 1) {
            a0 += __shfl_down_sync(0xffffffffu, a0, o);
            a1 += __shfl_down_sync(0xffffffffu, a1, o);
            a2 += __shfl_down_sync(0xffffffffu, a2, o);
            a3 += __shfl_down_sync(0xffffffffu, a3, o);
            a4 += __shfl_down_sync(0xffffffffu, a4, o);
        }
        if (lane == 0) {
            g_part[blockIdx.x][0] = a0;
            g_part[blockIdx.x][1] = a1;
            g_part[blockIdx.x][2] = a2;
            g_part[blockIdx.x][3] = a3;
            g_part[blockIdx.x][4] = a4;
        }
    }

    // --- last-done block merges partials and finalizes ---
    __shared__ int s_last;
    __syncthreads();
    if (tid == 0) {
        __threadfence();
        s_last = (atomicAdd(&g_done2, 1u) == gridDim.x - 1u);
    }
    __syncthreads();
    if (s_last) {
        __threadfence();
        double s0 = 0, s1 = 0, s2 = 0, s3 = 0, s4 = 0;
        for (int i = tid; i < (int)gridDim.x; i += NT) {
            s0 += g_part[i][0]; s1 += g_part[i][1]; s2 += g_part[i][2];
            s3 += g_part[i][3]; s4 += g_part[i][4];
        }
        for (int o = 16; o > 0; o >>= 1) {
            s0 += __shfl_down_sync(0xffffffffu, s0, o);
            s1 += __shfl_down_sync(0xffffffffu, s1, o);
            s2 += __shfl_down_sync(0xffffffffu, s2, o);
            s3 += __shfl_down_sync(0xffffffffu, s3, o);
            s4 += __shfl_down_sync(0xffffffffu, s4, o);
        }
        __shared__ double sh2[5][NT / 32];
        if (lane == 0) {
            sh2[0][wid] = s0; sh2[1][wid] = s1; sh2[2][wid] = s2;
            sh2[3][wid] = s3; sh2[4][wid] = s4;
        }
        __syncthreads();
        if (tid == 0) {
            s0 = s1 = s2 = s3 = s4 = 0.0;
            for (int w = 0; w < NT / 32; w++) {
                s0 += sh2[0][w]; s1 += sh2[1][w]; s2 += sh2[2][w];
                s3 += sh2[3][w]; s4 += sh2[4][w];
            }
            const double inv = 1.0 / (double)BN;
            const double d1r = s0 * inv;
            const double d1i = s1 * inv;
            const double d2  = s2 * inv;
            const double d3  = s3 * inv;
            const double mse = s4 / (double)(2 * BN);
            const double pr = d1r + d2 + d3;   // W1=W2=W3=1
            const double pi = d1i;
            const double lr = mse + 0.1 * pr;  // LMBDA = 0.1
            const double li = 0.1 * pi;
            if (out_size >= 10) {
                out[0] = (float)lr;  out[1] = (float)li;
                out[2] = (float)pr;  out[3] = (float)pi;
                out[4] = (float)d1r; out[5] = (float)d1i;
                out[6] = (float)d2;  out[7] = 0.f;
                out[8] = (float)d3;  out[9] = 0.f;
            } else {
                out[0] = (float)lr;
                if (out_size > 1) out[1] = (float)pr;
                if (out_size > 2) out[2] = (float)d1r;
                if (out_size > 3) out[3] = (float)d2;
                if (out_size > 4) out[4] = (float)d3;
            }
            g_done2 = 0u;
            g_epoch = g_epoch + 1ull;          // 46-bit epoch: never wraps
        }
    }
}

// ---------------------------------------------------------------------------
extern "C" void kernel_launch(void* const* d_in, const int* in_sizes, int n_in,
                              void* d_out, int out_size)
{
    const float* x       = (const float*)d_in[0];
    const float* ea      = (const float*)d_in[1];
    const int*   ei      = (const int*)  d_in[2];
    const float* outputs = (const float*)d_in[3];
    const float* labels  = (const float*)d_in[4];

    const int BN = in_sizes[3] / 2;        // B * N_BUSES
    const int B  = BN / N_BUSES;
    const int BE = in_sizes[2] / 2;        // B * E
    const int E  = BE / B;

    const int nbEdge = (BE / 2 + NT - 1) / NT;   // 2 edges/thread -> 375
    const int nbBus  = (BN / 2 + NT - 1) / NT;   // 2 buses/thread -> 125
    const int nbE = (nbEdge > B) ? nbEdge : B;   // ensure means blocks exist

    k1_build<<<nbE, NT>>>(x, ea, ei, outputs, B, BE, E);
    k2_terms<<<nbBus, NT>>>(x, outputs, labels, (float*)d_out, out_size, BN);
}

// round 12
// speedup vs baseline: 1.2516x; 1.0051x over previous
#include <cuda_runtime.h>
#include <cstdint>

#define N_BUSES 2000
#define MAX_BN     131072
#define MAX_B      64
#define MAX_LOSERS 8192
#define MAX_WARPS  8192
#define NT         256
#define NWPB       (NT / 32)
#define TAB_BITS   27
#define TAB_SIZE   (1 << TAB_BITS)      // keys < 32*2000*2000 < 2^27
#define EDGE_BITS  18
#define EDGE_MASK  0x3FFFFull

// Static device scratch (zero-initialized at module load; no runtime allocation).
__device__ unsigned long long g_tab[TAB_SIZE];    // (epoch<<18)|(edge+1); direct-mapped
__device__ int                g_losers[MAX_LOSERS];
__device__ int                g_nlos;
__device__ float2             g_YV[MAX_BN];       // per-bus YV accumulator (complex)
__device__ float2             g_Smean[MAX_B];
__device__ float              g_Vmmean[MAX_B];
__device__ float              g_partf[MAX_WARPS][5];  // per-WARP f32 partials (k2)
__device__ unsigned long long g_epoch;            // bumped once per call (k2 finalize)
__device__ unsigned           g_done1, g_done2;

__device__ __forceinline__ void red_add_v2(float2* addr, float vx, float vy)
{
    asm volatile("red.global.add.v2.f32 [%0], {%1, %2};"
                 :: "l"(addr), "f"(vx), "f"(vy) : "memory");
}

// ---------------------------------------------------------------------------
// K1: per-batch means | 2 edges/thread: scatter (red.v2) + dedup (atomicMax).
//     Last-done block subtracts loser contributions.
// ---------------------------------------------------------------------------
__global__ void k1_build(const float* __restrict__ x,
                         const float* __restrict__ ea,
                         const int*   __restrict__ ei,
                         const float* __restrict__ outputs,
                         int B, int BE, int E)
{
    const int tid = threadIdx.x;
    const int lane = tid & 31, wid = tid >> 5;
    const unsigned long long tag = g_epoch + 1ull;

    // --- blocks [0,B): per-batch means of S and Vm ---
    if (blockIdx.x < B) {
        const int b = blockIdx.x;
        float sr = 0.f, si = 0.f, vm = 0.f;
        for (int i = tid; i < N_BUSES; i += NT) {
            const float* p = x + (size_t)(b * N_BUSES + i) * 6;
            sr += p[0]; si += p[1]; vm += p[2];
        }
        for (int o = 16; o > 0; o >>= 1) {
            sr += __shfl_down_sync(0xffffffffu, sr, o);
            si += __shfl_down_sync(0xffffffffu, si, o);
            vm += __shfl_down_sync(0xffffffffu, vm, o);
        }
        __shared__ float shm[3][NWPB];
        if (lane == 0) { shm[0][wid] = sr; shm[1][wid] = si; shm[2][wid] = vm; }
        __syncthreads();
        if (wid == 0) {
            sr = (lane < NWPB) ? shm[0][lane] : 0.f;
            si = (lane < NWPB) ? shm[1][lane] : 0.f;
            vm = (lane < NWPB) ? shm[2][lane] : 0.f;
            for (int o = 4; o > 0; o >>= 1) {
                sr += __shfl_down_sync(0xffffffffu, sr, o);
                si += __shfl_down_sync(0xffffffffu, si, o);
                vm += __shfl_down_sync(0xffffffffu, vm, o);
            }
            if (lane == 0) {
                const float inv = 1.0f / (float)N_BUSES;
                g_Smean[b]  = make_float2(sr * inv, si * inv);
                g_Vmmean[b] = vm * inv;
            }
        }
    }

    // --- two edges per thread: batched loads, overlapped atomics ---
    const int e0 = 2 * (blockIdx.x * NT + tid);
    if (e0 + 1 < BE) {
        const int2  srcs = *(const int2*)(ei + e0);
        const int2  dsts = *(const int2*)(ei + BE + e0);
        const float4 aa  = *(const float4*)(ea + 2 * e0);

        const int iA = srcs.x % N_BUSES, jA = dsts.x % N_BUSES, bA = e0 / E;
        const int iB = srcs.y % N_BUSES, jB = dsts.y % N_BUSES, bB = (e0 + 1) / E;

        const float2 vA = *(const float2*)(outputs + 2 * (bA * N_BUSES + jA));
        const float2 vB = *(const float2*)(outputs + 2 * (bB * N_BUSES + jB));

        red_add_v2(&g_YV[bA * N_BUSES + iA],
                   aa.x * vA.x - aa.y * vA.y, aa.x * vA.y + aa.y * vA.x);
        red_add_v2(&g_YV[bB * N_BUSES + iB],
                   aa.z * vB.x - aa.w * vB.y, aa.z * vB.y + aa.w * vB.x);

        const int keyA = (bA * N_BUSES + iA) * N_BUSES + jA;
        const int keyB = (bB * N_BUSES + iB) * N_BUSES + jB;
        const unsigned long long nvA = (tag << EDGE_BITS) | (unsigned)(e0 + 1);
        const unsigned long long nvB = (tag << EDGE_BITS) | (unsigned)(e0 + 2);
        const unsigned long long oldA = atomicMax(&g_tab[keyA], nvA);
        const unsigned long long oldB = atomicMax(&g_tab[keyB], nvB);
        if ((oldA >> EDGE_BITS) == tag) {
            const int loser = (oldA > nvA) ? e0 : (int)(oldA & EDGE_MASK) - 1;
            const int li = atomicAdd(&g_nlos, 1);
            if (li < MAX_LOSERS) g_losers[li] = loser;
        }
        if ((oldB >> EDGE_BITS) == tag) {
            const int loser = (oldB > nvB) ? (e0 + 1) : (int)(oldB & EDGE_MASK) - 1;
            const int li = atomicAdd(&g_nlos, 1);
            if (li < MAX_LOSERS) g_losers[li] = loser;
        }
    } else if (e0 < BE) {
        const int i = ei[e0] % N_BUSES, j = ei[BE + e0] % N_BUSES, b = e0 / E;
        const float2 av = *(const float2*)(ea + 2 * e0);
        const float2 v  = *(const float2*)(outputs + 2 * (b * N_BUSES + j));
        red_add_v2(&g_YV[b * N_BUSES + i],
                   av.x * v.x - av.y * v.y, av.x * v.y + av.y * v.x);
        const int key = (b * N_BUSES + i) * N_BUSES + j;
        const unsigned long long nv = (tag << EDGE_BITS) | (unsigned)(e0 + 1);
        const unsigned long long old = atomicMax(&g_tab[key], nv);
        if ((old >> EDGE_BITS) == tag) {
            const int loser = (old > nv) ? e0 : (int)(old & EDGE_MASK) - 1;
            const int li = atomicAdd(&g_nlos, 1);
            if (li < MAX_LOSERS) g_losers[li] = loser;
        }
    }

    // --- last-done block subtracts loser contributions ---
    __shared__ int s_last;
    __syncthreads();
    if (tid == 0) {
        __threadfence();
        s_last = (atomicAdd(&g_done1, 1u) == gridDim.x - 1u);
    }
    __syncthreads();
    if (s_last) {
        __threadfence();
        const int n = g_nlos;
        for (int t = tid; t < n && t < MAX_LOSERS; t += NT) {
            const int le = g_losers[t];
            const int i = ei[le] % N_BUSES, j = ei[BE + le] % N_BUSES, b = le / E;
            const float2 av = *(const float2*)(ea + 2 * le);
            const float2 v  = *(const float2*)(outputs + 2 * (b * N_BUSES + j));
            red_add_v2(&g_YV[b * N_BUSES + i],
                       -(av.x * v.x - av.y * v.y), -(av.x * v.y + av.y * v.x));
        }
        __syncthreads();
        if (tid == 0) { g_done1 = 0u; g_nlos = 0; }
    }
}

// ---------------------------------------------------------------------------
// K2: 2 buses/thread, all-f32 hot path, ONE reduction stage (warp -> gmem);
//     last-done block merges per-warp partials in f64 and finalizes.
// ---------------------------------------------------------------------------
__global__ void k2_terms(const float* __restrict__ x,
                         const float* __restrict__ outputs,
                         const float* __restrict__ labels,
                         float* __restrict__ out, int out_size, int BN)
{
    const int tid = threadIdx.x;
    const int lane = tid & 31, wid = tid >> 5;
    const int i0 = 2 * (blockIdx.x * NT + tid);
    float a0 = 0.f, a1 = 0.f, a2 = 0.f, a3 = 0.f, a4 = 0.f;

    if (i0 + 1 < BN) {
        const float4 vv  = *(const float4*)(outputs + 2 * i0);
        const float4 ll  = *(const float4*)(labels  + 2 * i0);
        const float4 yv2 = *(const float4*)&g_YV[i0];
        const float4* px = (const float4*)(x + (size_t)i0 * 6);
        const float4 xa = px[0], xb = px[1], xc = px[2];
        *(float4*)&g_YV[i0] = make_float4(0.f, 0.f, 0.f, 0.f);   // clean for next call

        const int b = i0 / N_BUSES;      // i0 even => both buses same batch
        const float2 sm = g_Smean[b];
        const float smn = 1.f / sqrtf(sm.x * sm.x + sm.y * sm.y);
        const float vmm = 1.f / g_Vmmean[b];

        {   // bus A: x row = {xa.x,xa.y,xa.z,xa.w,xb.x,xb.y}
            const float vr = vv.x, vi = vv.y;
            const float sr = xa.x, si = xa.y, vm = xa.z;
            const float bt0 = xa.w, bt1 = xb.x, bt2 = xb.y;
            const float sp_re = vr * yv2.x + vi * yv2.y;
            const float sp_im = vi * yv2.x - vr * yv2.y;
            const float sn = (sr != 0.f || si != 0.f)
                           ? (1.f / sqrtf(sr * sr + si * si)) : smn;
            const float dr = sp_re - sr, di = sp_im - si;
            a0 += sn * ((dr * dr - di * di) * bt0 + dr * dr * bt1);
            a1 += sn * (2.f * dr * di) * bt0;
            const float vminv = (vm != 0.f) ? (1.f / vm) : vmm;
            const float vmag  = sqrtf(vr * vr + vi * vi);
            a2 += fabsf(vmag * (bt1 + bt2) - vm) * vminv;
            a3 += fabsf(vi * bt2) * vminv;
            const float e0 = vr - ll.x, e1 = vi - ll.y;
            a4 += e0 * e0 + e1 * e1;
        }
        {   // bus B: x row = {xb.z,xb.w,xc.x,xc.y,xc.z,xc.w}
            const float vr = vv.z, vi = vv.w;
            const float sr = xb.z, si = xb.w, vm = xc.x;
            const float bt0 = xc.y, bt1 = xc.z, bt2 = xc.w;
            const float sp_re = vr * yv2.z + vi * yv2.w;
            const float sp_im = vi * yv2.z - vr * yv2.w;
            const float sn = (sr != 0.f || si != 0.f)
                           ? (1.f / sqrtf(sr * sr + si * si)) : smn;
            const float dr = sp_re - sr, di = sp_im - si;
            a0 += sn * ((dr * dr - di * di) * bt0 + dr * dr * bt1);
            a1 += sn * (2.f * dr * di) * bt0;
            const float vminv = (vm != 0.f) ? (1.f / vm) : vmm;
            const float vmag  = sqrtf(vr * vr + vi * vi);
            a2 += fabsf(vmag * (bt1 + bt2) - vm) * vminv;
            a3 += fabsf(vi * bt2) * vminv;
            const float e0 = vr - ll.z, e1 = vi - ll.w;
            a4 += e0 * e0 + e1 * e1;
        }
    } else if (i0 < BN) {
        const int b = i0 / N_BUSES;
        const float2 v2 = *(const float2*)(outputs + 2 * i0);
        const float2 l2 = *(const float2*)(labels + 2 * i0);
        const float2 yv = g_YV[i0];
        g_YV[i0] = make_float2(0.f, 0.f);
        const float* p = x + (size_t)i0 * 6;
        const float sr = p[0], si = p[1], vm = p[2];
        const float bt0 = p[3], bt1 = p[4], bt2 = p[5];
        const float sp_re = v2.x * yv.x + v2.y * yv.y;
        const float sp_im = v2.y * yv.x - v2.x * yv.y;
        float sn;
        if (sr != 0.f || si != 0.f) sn = 1.f / sqrtf(sr * sr + si * si);
        else { const float2 sm = g_Smean[b]; sn = 1.f / sqrtf(sm.x * sm.x + sm.y * sm.y); }
        const float dr = sp_re - sr, di = sp_im - si;
        a0 = sn * ((dr * dr - di * di) * bt0 + dr * dr * bt1);
        a1 = sn * (2.f * dr * di) * bt0;
        const float vminv = (vm != 0.f) ? (1.f / vm) : (1.f / g_Vmmean[b]);
        const float vmag  = sqrtf(v2.x * v2.x + v2.y * v2.y);
        a2 = fabsf(vmag * (bt1 + bt2) - vm) * vminv;
        a3 = fabsf(v2.y * bt2) * vminv;
        const float e0 = v2.x - l2.x, e1 = v2.y - l2.y;
        a4 = e0 * e0 + e1 * e1;
    }

    // single-stage reduction: warp shuffle -> per-warp gmem partial
    for (int o = 16; o > 0; o >>= 1) {
        a0 += __shfl_down_sync(0xffffffffu, a0, o);
        a1 += __shfl_down_sync(0xffffffffu, a1, o);
        a2 += __shfl_down_sync(0xffffffffu, a2, o);
        a3 += __shfl_down_sync(0xffffffffu, a3, o);
        a4 += __shfl_down_sync(0xffffffffu, a4, o);
    }
    if (lane == 0) {
        float* p = g_partf[blockIdx.x * NWPB + wid];
        p[0] = a0; p[1] = a1; p[2] = a2; p[3] = a3; p[4] = a4;
    }

    // --- last-done block merges per-warp partials (f64) and finalizes ---
    __shared__ int s_last;
    __syncthreads();
    if (tid == 0) {
        __threadfence();
        s_last = (atomicAdd(&g_done2, 1u) == gridDim.x - 1u);
    }
    __syncthreads();
    if (s_last) {
        __threadfence();
        const int nw = (int)gridDim.x * NWPB;
        double s0 = 0, s1 = 0, s2 = 0, s3 = 0, s4 = 0;
        for (int i = tid; i < nw; i += NT) {
            const float* p = g_partf[i];
            s0 += (double)p[0]; s1 += (double)p[1]; s2 += (double)p[2];
            s3 += (double)p[3]; s4 += (double)p[4];
        }
        for (int o = 16; o > 0; o >>= 1) {
            s0 += __shfl_down_sync(0xffffffffu, s0, o);
            s1 += __shfl_down_sync(0xffffffffu, s1, o);
            s2 += __shfl_down_sync(0xffffffffu, s2, o);
            s3 += __shfl_down_sync(0xffffffffu, s3, o);
            s4 += __shfl_down_sync(0xffffffffu, s4, o);
        }
        __shared__ double sh2[5][NWPB];
        if (lane == 0) {
            sh2[0][wid] = s0; sh2[1][wid] = s1; sh2[2][wid] = s2;
            sh2[3][wid] = s3; sh2[4][wid] = s4;
        }
        __syncthreads();
        if (tid == 0) {
            s0 = s1 = s2 = s3 = s4 = 0.0;
            for (int w = 0; w < NWPB; w++) {
                s0 += sh2[0][w]; s1 += sh2[1][w]; s2 += sh2[2][w];
                s3 += sh2[3][w]; s4 += sh2[4][w];
            }
            const double inv = 1.0 / (double)BN;
            const double d1r = s0 * inv;
            const double d1i = s1 * inv;
            const double d2  = s2 * inv;
            const double d3  = s3 * inv;
            const double mse = s4 / (double)(2 * BN);
            const double pr = d1r + d2 + d3;   // W1=W2=W3=1
            const double pi = d1i;
            const double lr = mse + 0.1 * pr;  // LMBDA = 0.1
            const double li = 0.1 * pi;
            if (out_size >= 10) {
                out[0] = (float)lr;  out[1] = (float)li;
                out[2] = (float)pr;  out[3] = (float)pi;
                out[4] = (float)d1r; out[5] = (float)d1i;
                out[6] = (float)d2;  out[7] = 0.f;
                out[8] = (float)d3;  out[9] = 0.f;
            } else {
                out[0] = (float)lr;
                if (out_size > 1) out[1] = (float)pr;
                if (out_size > 2) out[2] = (float)d1r;
                if (out_size > 3) out[3] = (float)d2;
                if (out_size > 4) out[4] = (float)d3;
            }
            g_done2 = 0u;
            g_epoch = g_epoch + 1ull;          // 46-bit epoch: never wraps
        }
    }
}

// ---------------------------------------------------------------------------
extern "C" void kernel_launch(void* const* d_in, const int* in_sizes, int n_in,
                              void* d_out, int out_size)
{
    const float* x       = (const float*)d_in[0];
    const float* ea      = (const float*)d_in[1];
    const int*   ei      = (const int*)  d_in[2];
    const float* outputs = (const float*)d_in[3];
    const float* labels  = (const float*)d_in[4];

    const int BN = in_sizes[3] / 2;        // B * N_BUSES
    const int B  = BN / N_BUSES;
    const int BE = in_sizes[2] / 2;        // B * E
    const int E  = BE / B;

    const int nbEdge = (BE / 2 + NT - 1) / NT;   // 2 edges/thread
    const int nbBus  = (BN / 2 + NT - 1) / NT;   // 2 buses/thread
    const int nbE = (nbEdge > B) ? nbEdge : B;

    k1_build<<<nbE, NT>>>(x, ea, ei, outputs, B, BE, E);
    k2_terms<<<nbBus, NT>>>(x, outputs, labels, (float*)d_out, out_size, BN);
}